// round 17
// baseline (speedup 1.0000x reference)
#include <cuda_runtime.h>
#include <cstdint>

#define DD 160
#define NN 82944
#define BB 4
#define WTILE 64            /* columns per tile */
#define G 8                 /* d-groups per column */
#define DG 20               /* rows per group */
#define NTH 512             /* G * WTILE */
#define PBLKS 288           /* persistent blocks (288 x 18 = 5184 tiles) */
#define TPB 18              /* tiles per block */
#define BLKS_PER_B 72       /* blocks per batch */
#define EPSV 1e-6f
#define NBLKF 81            /* NN / 1024 for float4x256 final kernel */

// Scratch state (device globals: no allocation allowed)
__device__ float g_c[BB * NN];                 // coef
__device__ float g_v[BB * DD];                 // bases vector
__device__ float g_s[BB];                      // ||v||^2
__device__ float g_wp[BB * BLKS_PER_B * DD];   // per-block w partials
__device__ float g_tp[BB * BLKS_PER_B];        // per-block t partials

// ---------------------------------------------------------------------------
// init: v = bases, s = ||v||^2
// ---------------------------------------------------------------------------
__global__ void init_kernel(const float* __restrict__ bases) {
    int b = blockIdx.x, d = threadIdx.x;
    __shared__ float sh[DD];
    float v = bases[b * DD + d];
    g_v[b * DD + d] = v;
    sh[d] = v * v;
    __syncthreads();
    if (d == 0) {
        float s = 0.f;
        for (int i = 0; i < DD; i++) s += sh[i];
        g_s[b] = s;
    }
}

// ---------------------------------------------------------------------------
// One NMF step: 2x512 threads per SM, register-resident X, ONE barrier/tile.
// Thread (g,c) loads its 20-row column segment once (coalesced full-line
// LDGs), posts a u-partial into the parity-selected u_sh buffer, barriers,
// then EVERY thread redundantly combines the 8 partials to form c_new
// (deterministic) and folds its registers into w accumulators.
// ---------------------------------------------------------------------------
__global__ void __launch_bounds__(NTH, 2) step_kernel(const float* __restrict__ x,
                                                      int first) {
    __shared__ float v_sh[DD];
    __shared__ float u_sh[2][NTH];
    __shared__ float wred[16][DG];
    __shared__ float tred[2];

    int p = blockIdx.x, tid = threadIdx.x;
    int lane = tid & 31, wrp = tid >> 5;
    int g = tid >> 6;            // d-group 0..7
    int c = tid & 63;            // column within tile
    int b = p / BLKS_PER_B, pb = p % BLKS_PER_B;
    int blk0 = pb * TPB;

    for (int i = tid; i < DD; i += NTH) v_sh[i] = g_v[b * DD + i];
    float s = g_s[b];
    __syncthreads();

    const float* xp0 = x + ((size_t)b * DD + g * DG) * NN
                         + (size_t)blk0 * WTILE + c;
    const float* vg = v_sh + g * DG;

    float wacc[DG];
#pragma unroll
    for (int k = 0; k < DG; k++) wacc[k] = 0.f;
    float tacc = 0.f;

    for (int i = 0; i < TPB; i++) {
        // ---- prefetch old coef early (overlaps the X loads below)
        size_t cidx = (size_t)b * NN + (size_t)(blk0 + i) * WTILE + c;
        float cold = first ? 1.f : __ldg(&g_c[cidx]);

        const float* xp = xp0 + (size_t)i * WTILE;

        // ---- load 20 rows of this column into registers (batched LDGs)
        float xr[DG];
#pragma unroll
        for (int k = 0; k < DG; k++) xr[k] = xp[(size_t)k * NN];

        // ---- u partial
        float u0 = 0.f, u1 = 0.f, u2 = 0.f, u3 = 0.f;
#pragma unroll
        for (int k = 0; k < DG; k += 4) {
            u0 = fmaf(xr[k + 0], vg[k + 0], u0);
            u1 = fmaf(xr[k + 1], vg[k + 1], u1);
            u2 = fmaf(xr[k + 2], vg[k + 2], u2);
            u3 = fmaf(xr[k + 3], vg[k + 3], u3);
        }
        const float* ub = u_sh[i & 1];
        u_sh[i & 1][tid] = (u0 + u1) + (u2 + u3);
        __syncthreads();   // the ONLY barrier in the tile loop

        // ---- every thread combines the 8 partials (deterministic, identical)
        float u = ((ub[c]       + ub[c + 64])  + (ub[c + 128] + ub[c + 192]))
                + ((ub[c + 256] + ub[c + 320]) + (ub[c + 384] + ub[c + 448]));
        float cn = cold * u / (cold * s + EPSV);
        if (g == 0) {
            g_c[cidx] = cn;
            tacc = fmaf(cn, cn, tacc);
        }

        // ---- fold registers into w accumulators
#pragma unroll
        for (int k = 0; k < DG; k++) wacc[k] = fmaf(xr[k], cn, wacc[k]);
        // next iteration writes the OTHER u_sh buffer -> no extra barrier
    }

    // ---- end-of-step reductions (once per block)
    if (g == 0) {
#pragma unroll
        for (int off = 16; off; off >>= 1)
            tacc += __shfl_xor_sync(0xffffffffu, tacc, off);
        if (lane == 0) tred[wrp] = tacc;
    }
#pragma unroll
    for (int k = 0; k < DG; k++) {
        float a = wacc[k];
#pragma unroll
        for (int off = 16; off; off >>= 1)
            a += __shfl_xor_sync(0xffffffffu, a, off);
        if (lane == 0) wred[wrp][k] = a;   // warp wrp covers g = wrp/2
    }
    __syncthreads();
    if (tid == 0) g_tp[b * BLKS_PER_B + pb] = tred[0] + tred[1];
    if (tid < DD) {
        int gg = tid / DG, k = tid % DG;
        g_wp[(size_t)(b * BLKS_PER_B + pb) * DD + tid] =
            wred[2 * gg][k] + wred[2 * gg + 1][k];
    }
}

// ---------------------------------------------------------------------------
// v update: sum 72 partials, v = v*w/(v*t+eps), s = ||v||^2
// ---------------------------------------------------------------------------
__global__ void vupdate_kernel() {
    __shared__ float shs[DD];
    __shared__ float tsh;
    int b = blockIdx.x, tid = threadIdx.x;  // 160 threads

    float w = 0.f;
    for (int j = 0; j < BLKS_PER_B; j++)
        w += g_wp[(size_t)(b * BLKS_PER_B + j) * DD + tid];
    if (tid == 0) {
        float t = 0.f;
        for (int j = 0; j < BLKS_PER_B; j++) t += g_tp[b * BLKS_PER_B + j];
        tsh = t;
    }
    __syncthreads();

    float vd = g_v[b * DD + tid];
    float vn = vd * w / (vd * tsh + EPSV);
    g_v[b * DD + tid] = vn;
    shs[tid] = vn * vn;
    __syncthreads();
    if (tid == 0) {
        float s = 0.f;
        for (int i = 0; i < DD; i++) s += shs[i];
        g_s[b] = s;
    }
}

// ---------------------------------------------------------------------------
// Final: u = X^T v, c' = c*u/(c*s+eps), out = v c'^T.
// float4 per thread, 256-thread blocks.
// ---------------------------------------------------------------------------
__global__ void __launch_bounds__(256) final_kernel(const float* __restrict__ x,
                                                    float* __restrict__ out) {
    __shared__ float v_sh[DD];
    int b = blockIdx.y, tid = threadIdx.x;
    size_t n0 = (size_t)blockIdx.x * 1024 + (size_t)tid * 4;

    for (int i = tid; i < DD; i += 256) v_sh[i] = g_v[b * DD + i];
    __syncthreads();
    float s = g_s[b];

    const float* xb = x + (size_t)b * DD * NN + n0;
    float* ob = out + (size_t)b * DD * NN + n0;

    float4 u = make_float4(0.f, 0.f, 0.f, 0.f);
#pragma unroll 16
    for (int d = 0; d < DD; d++) {
        float4 xv = *reinterpret_cast<const float4*>(xb + (size_t)d * NN);
        float vd = v_sh[d];
        u.x = fmaf(xv.x, vd, u.x);
        u.y = fmaf(xv.y, vd, u.y);
        u.z = fmaf(xv.z, vd, u.z);
        u.w = fmaf(xv.w, vd, u.w);
    }

    float4 co = *reinterpret_cast<const float4*>(g_c + (size_t)b * NN + n0);
    float4 cn;
    cn.x = co.x * u.x / (co.x * s + EPSV);
    cn.y = co.y * u.y / (co.y * s + EPSV);
    cn.z = co.z * u.z / (co.z * s + EPSV);
    cn.w = co.w * u.w / (co.w * s + EPSV);

#pragma unroll 16
    for (int d = 0; d < DD; d++) {
        float vd = v_sh[d];
        float4 o = make_float4(vd * cn.x, vd * cn.y, vd * cn.z, vd * cn.w);
        *reinterpret_cast<float4*>(ob + (size_t)d * NN) = o;
    }
}

// ---------------------------------------------------------------------------
extern "C" void kernel_launch(void* const* d_in, const int* in_sizes, int n_in,
                              void* d_out, int out_size) {
    const float* x = (const float*)d_in[0];
    const float* bases = (const float*)d_in[1];
    float* out = (float*)d_out;

    init_kernel<<<BB, DD>>>(bases);
    for (int s = 0; s < 4; s++) {
        step_kernel<<<PBLKS, NTH>>>(x, s == 0);
        vupdate_kernel<<<BB, DD>>>();
    }
    final_kernel<<<dim3(NBLKF, BB), 256>>>(x, out);
}